// round 7
// baseline (speedup 1.0000x reference)
#include <cuda_runtime.h>
#include <math.h>

#define BB 4
#define NA 50
#define SZ 256
#define SS (SZ*SZ)
#define NC 32
#define PP 512
#define CEN 127.5f
#define NZ 8                       // radon band splits

typedef unsigned long long u64;

// ---- packed f32x2 helpers (sm_103a dual-rate fp32 path) ----
__device__ __forceinline__ u64 pk2(float lo, float hi) {
    u64 r; asm("mov.b64 %0, {%1, %2};" : "=l"(r) : "f"(lo), "f"(hi)); return r;
}
__device__ __forceinline__ u64 fma2(u64 a, u64 b, u64 c) {
    u64 d; asm("fma.rn.f32x2 %0, %1, %2, %3;" : "=l"(d) : "l"(a), "l"(b), "l"(c)); return d;
}
__device__ __forceinline__ void unpk2(u64 v, float& lo, float& hi) {
    asm("mov.b64 {%0, %1}, %2;" : "=f"(lo), "=f"(hi) : "l"(v));
}

// ---------------- scratch (static device allocations) ----------------
__device__ float g_part[NZ*BB*NA*SZ];    // radon partial sums per band
__device__ float g_filt[BB*NA*SZ];       // filtered sinogram (scaled)
__device__ float g_h1[BB*NC*SS];         // conv1 output
__device__ float g_h2[BB*NC*SS];         // conv2 output
__device__ float g_up[BB*SS];            // fallback y_img_update buffer

// ---------------- 1. radon forward: band-tiled, mask fused ----------------
// grid (NA, BB, NZ), 256 threads = detector bin s.
__global__ void __launch_bounds__(256) k_radon(const float* __restrict__ yprev,
                                               const float* __restrict__ angles) {
    __shared__ float s_band[33][257];
    int a = blockIdx.x, b = blockIdx.y, z = blockIdx.z;
    int s = threadIdx.x;
    int y0 = z * 32;
    int lo = (z == 0) ? -1 : y0;
    int hi = y0 + 32;

    // cooperative band load with circle mask fused (row 256 zero-padded)
    const float* im = &yprev[b * SS];
    float dxm = (float)s - CEN;
    #pragma unroll
    for (int i = 0; i < 33; ++i) {
        int gy = y0 + i;
        float dym = (float)gy - CEN;
        float m = (dym * dym + dxm * dxm <= 16384.0f) ? 1.0f : 0.0f;
        s_band[i][s] = (gy <= 255) ? im[gy * SZ + s] * m : 0.0f;
    }
    __syncthreads();

    float ca, sa;
    __sincosf(angles[a], &sa, &ca);
    float sf = (float)s - CEN;
    float rowA = sf * sa - CEN * ca + CEN;   // row(t) = rowA + t*ca
    float colA = sf * ca + CEN * sa + CEN;   // col(t) = colA - t*sa

    float tmin, tmax;
    if (fabsf(ca) > 1e-6f) {
        float t1 = ((float)lo - 0.5f - rowA) / ca;
        float t2 = ((float)hi + 0.5f - rowA) / ca;
        tmin = fminf(t1, t2) - 1.0f;
        tmax = fmaxf(t1, t2) + 1.0f;
    } else {
        bool inb = (rowA >= (float)lo - 1.0f) && (rowA < (float)hi + 1.0f);
        tmin = inb ? 0.0f : 1.0f;
        tmax = inb ? 255.0f : 0.0f;
    }
    int ts = max(0, (int)floorf(tmin));
    int te = min(255, (int)ceilf(tmax));

    float sum = 0.0f;
    for (int t = ts; t <= te; ++t) {
        float row = rowA + (float)t * ca;
        float rf = floorf(row);
        int r0 = (int)rf;
        if (r0 < lo || r0 >= hi) continue;        // exact ownership test
        float wr = row - rf;
        float col = colA - (float)t * sa;
        float cf = floorf(col);
        int c0 = (int)cf;
        float wc = col - cf;
        int c0c = min(max(c0, 0), 255);
        int c1c = min(max(c0 + 1, 0), 255);
        float mc0 = (c0 == c0c) ? 1.0f : 0.0f;
        float mc1 = (c0 + 1 == c1c) ? 1.0f : 0.0f;
        float mr0 = (r0 >= 0) ? 1.0f : 0.0f;      // r0 == -1 edge
        int lr = r0 - y0;
        int lrc = max(lr, 0);
        float v00 = s_band[lrc][c0c],     v01 = s_band[lrc][c1c];
        float v10 = s_band[lr + 1][c0c],  v11 = s_band[lr + 1][c1c];
        float top = mc0 * (1.0f - wc) * v00 + mc1 * wc * v01;
        float bot = mc0 * (1.0f - wc) * v10 + mc1 * wc * v11;
        sum += mr0 * (1.0f - wr) * top + wr * bot;
    }
    g_part[((z * BB + b) * NA + a) * SZ + s] = sum;
}

// ---------------- 2. ramp filter: analytic taps + fold partials ------------
// h[0]=0.5, h[even!=0]=0, h[odd m] = -2/(PP^2 sin^2(pi m/PP))
__device__ __forceinline__ float hval(int m) {
    if (m == 0) return 0.5f;
    if ((m & 1) == 0) return 0.0f;
    float sv = sinf((float)M_PI * (float)m / (float)PP);
    return -2.0f / ((float)PP * (float)PP * sv * sv);
}
__global__ void k_filter(const float* __restrict__ x_sino) {
    __shared__ float sd[SZ];
    __shared__ float sh[PP];
    int a = blockIdx.x, b = blockIdx.y;
    int n = threadIdx.x;
    int base = (b * NA + a) * SZ + n;
    float d = -x_sino[base];
    #pragma unroll
    for (int z = 0; z < NZ; ++z) d += g_part[((z * BB + b) * NA + a) * SZ + n];
    sd[n] = d;
    sh[n] = hval(n);
    sh[n + 256] = hval(n + 256);
    __syncthreads();
    float acc = 0.5f * sd[n];
    int m0 = (n & 1) ^ 1;
    #pragma unroll 8
    for (int j = 0; j < 128; ++j) {
        int m = m0 + 2 * j;
        acc += sd[m] * sh[(n - m + PP) & (PP - 1)];
    }
    g_filt[base] = acc * (float)(M_PI / (2.0 * NA));
}

// ---------------- 3. backprojection + update (2 rows/block) ----------------
__global__ void __launch_bounds__(512) k_backproj(const float* __restrict__ yprev,
                                                  const float* __restrict__ angles,
                                                  const float* __restrict__ step,
                                                  float* __restrict__ out_up) {
    __shared__ float s_sino[25 * SZ];
    __shared__ float s_cos[NA], s_sin[NA];
    int b = blockIdx.y;
    int tid = threadIdx.x;
    int j = tid & 255, half = tid >> 8;
    int i = blockIdx.x * 2 + half;
    if (tid < NA) { s_cos[tid] = cosf(angles[tid]); s_sin[tid] = sinf(angles[tid]); }
    __syncthreads();
    float xx = (float)j - CEN, yy = (float)i - CEN;
    float acc = 0.0f;
    for (int ch = 0; ch < 2; ++ch) {
        for (int k = tid; k < 25 * SZ; k += 512) {
            s_sino[k] = g_filt[(b * NA + ch * 25) * SZ + k];
        }
        __syncthreads();
        #pragma unroll 5
        for (int al = 0; al < 25; ++al) {
            int a = ch * 25 + al;
            float det = xx * s_cos[a] + yy * s_sin[a] + CEN;
            float df = floorf(det);
            int i0 = (int)df;
            i0 = i0 < 0 ? 0 : (i0 > SZ - 2 ? SZ - 2 : i0);
            float w = det - (float)i0;
            float v = s_sino[al * SZ + i0] * (1.0f - w) + s_sino[al * SZ + i0 + 1] * w;
            if (det >= 0.0f && det <= (float)(SZ - 1)) acc += v;
        }
        __syncthreads();
    }
    float m = (xx*xx + yy*yy <= 16384.0f) ? 1.0f : 0.0f;
    int o = b * SS + i * SZ + j;
    out_up[o] = yprev[o] + step[0] * (acc * m);
}

// ---------------- 4. conv1: 2 -> 32, 3x3 SAME, ReLU (f32x2) ----------------
__global__ void k_conv1(const float* __restrict__ yup,
                        const float* __restrict__ ycat,
                        const float* __restrict__ w1,
                        const float* __restrict__ b1) {
    __shared__ __align__(16) float s_w2[18 * 32];
    __shared__ __align__(8)  float s_b[NC];
    int tid = threadIdx.x;
    for (int idx = tid; idx < 18 * 32; idx += 256) {
        int kk = idx >> 5, oc = idx & 31;
        s_w2[idx] = w1[oc * 18 + kk];
    }
    if (tid < NC) s_b[tid] = b1[tid];
    __syncthreads();
    int idx = blockIdx.x * 256 + tid;
    int b = idx >> 16;
    int p = idx & (SS - 1);
    int i = p >> 8, j = p & 255;
    float iv[18];
    #pragma unroll
    for (int ky = 0; ky < 3; ++ky) {
        #pragma unroll
        for (int kx = 0; kx < 3; ++kx) {
            int y = i + ky - 1, x = j + kx - 1;
            bool ok = (y >= 0) && (y < SZ) && (x >= 0) && (x < SZ);
            int gi = b * SS + y * SZ + x;
            iv[ky*3+kx]     = ok ? yup[gi]  : 0.0f;
            iv[9 + ky*3+kx] = ok ? ycat[gi] : 0.0f;
        }
    }
    u64 acc2[16];
    #pragma unroll
    for (int op = 0; op < 16; ++op) acc2[op] = ((const u64*)s_b)[op];
    #pragma unroll
    for (int k = 0; k < 18; ++k) {
        u64 ib = pk2(iv[k], iv[k]);
        const ulonglong2* wrow = (const ulonglong2*)&s_w2[k * 32];
        #pragma unroll
        for (int g = 0; g < 8; ++g) {
            ulonglong2 wv = wrow[g];
            acc2[2*g]   = fma2(wv.x, ib, acc2[2*g]);
            acc2[2*g+1] = fma2(wv.y, ib, acc2[2*g+1]);
        }
    }
    #pragma unroll
    for (int op = 0; op < 16; ++op) {
        float lo, hi; unpk2(acc2[op], lo, hi);
        g_h1[((b * NC + 2*op)     << 16) + p] = fmaxf(lo, 0.0f);
        g_h1[((b * NC + 2*op + 1) << 16) + p] = fmaxf(hi, 0.0f);
    }
}

// ---------------- 5. conv2: 32 -> 32, 3x3 SAME, ReLU (f32x2, 8 px/thread) --
// Tile 64(x) x 8(y). 256 threads: q=tid&7 (x-octet of 8px... 8 groups),
// r=(tid>>3)&7 (row), og=tid>>6 (8-oc group). ic chunked by 8.
#define ICH2 8
#define RW2 68   // padded row width (66 used; 68*4B = 16B-aligned rows)
__global__ void __launch_bounds__(256) k_conv2(const float* __restrict__ w2,
                                               const float* __restrict__ b2) {
    __shared__ __align__(16) float s_w[ICH2 * 9 * 32];     // [ic][k][oc]
    __shared__ __align__(16) float s_in[ICH2 * 10 * RW2];  // [ic][row][col]
    __shared__ float s_b[NC];
    int tid = threadIdx.x;
    int q = tid & 7, r = (tid >> 3) & 7, og = tid >> 6;
    int b = blockIdx.z;
    int gx0 = blockIdx.x * 64 - 1;
    int gy0 = blockIdx.y * 8 - 1;
    if (tid < NC) s_b[tid] = b2[tid];

    u64 acc2[4][8];   // [oc-pair within og][px]
    #pragma unroll
    for (int op = 0; op < 4; ++op)
        #pragma unroll
        for (int p = 0; p < 8; ++p) acc2[op][p] = 0ULL;

    for (int cc = 0; cc < 4; ++cc) {
        int icb = cc * ICH2;
        __syncthreads();
        for (int idx = tid; idx < ICH2 * 288; idx += 256) {
            int ic = idx / 288, rem = idx % 288;
            int k = rem >> 5, oc = rem & 31;
            s_w[idx] = w2[oc * 288 + (icb + ic) * 9 + k];
        }
        for (int idx = tid; idx < ICH2 * 10 * RW2; idx += 256) {
            int ic = idx / (10 * RW2), rem = idx % (10 * RW2);
            int rr = rem / RW2, ccx = rem % RW2;
            int gy = gy0 + rr, gx = gx0 + ccx;
            bool ok = (ccx < 66) && (gy >= 0) && (gy < SZ) && (gx >= 0) && (gx < SZ);
            s_in[idx] = ok ? g_h1[((b * NC + icb + ic) << 16) + gy * SZ + gx] : 0.0f;
        }
        __syncthreads();

        for (int ic = 0; ic < ICH2; ++ic) {
            const float* inb = &s_in[ic * 10 * RW2];
            const float* wb  = &s_w[ic * 288];
            #pragma unroll
            for (int ky = 0; ky < 3; ++ky) {
                const float* rowp = inb + (r + ky) * RW2 + q * 8;
                float4 va = *(const float4*)rowp;
                float4 vb = *(const float4*)(rowp + 4);
                float2 vc = *(const float2*)(rowp + 8);
                float ivf[10] = {va.x, va.y, va.z, va.w,
                                 vb.x, vb.y, vb.z, vb.w, vc.x, vc.y};
                u64 ivp[10];
                #pragma unroll
                for (int m = 0; m < 10; ++m) ivp[m] = pk2(ivf[m], ivf[m]);
                #pragma unroll
                for (int kx = 0; kx < 3; ++kx) {
                    const ulonglong2 wv0 = *(const ulonglong2*)&wb[(ky*3+kx)*32 + og*8];
                    const ulonglong2 wv1 = *(const ulonglong2*)&wb[(ky*3+kx)*32 + og*8 + 4];
                    u64 wp[4] = {wv0.x, wv0.y, wv1.x, wv1.y};
                    #pragma unroll
                    for (int op = 0; op < 4; ++op)
                        #pragma unroll
                        for (int p = 0; p < 8; ++p)
                            acc2[op][p] = fma2(wp[op], ivp[kx + p], acc2[op][p]);
                }
            }
        }
    }
    int gy = blockIdx.y * 8 + r;
    int gxb = blockIdx.x * 64 + q * 8;
    #pragma unroll
    for (int op = 0; op < 4; ++op) {
        int oc0 = og * 8 + 2 * op;
        float blo = s_b[oc0], bhi = s_b[oc0 + 1];
        float flo[8], fhi[8];
        #pragma unroll
        for (int p = 0; p < 8; ++p) {
            float lo, hi; unpk2(acc2[op][p], lo, hi);
            flo[p] = fmaxf(lo + blo, 0.0f);
            fhi[p] = fmaxf(hi + bhi, 0.0f);
        }
        float* olo = &g_h2[((b * NC + oc0)     << 16) + gy * SZ + gxb];
        float* ohi = &g_h2[((b * NC + oc0 + 1) << 16) + gy * SZ + gxb];
        *(float4*)olo       = make_float4(flo[0], flo[1], flo[2], flo[3]);
        *(float4*)(olo + 4) = make_float4(flo[4], flo[5], flo[6], flo[7]);
        *(float4*)ohi       = make_float4(fhi[0], fhi[1], fhi[2], fhi[3]);
        *(float4*)(ohi + 4) = make_float4(fhi[4], fhi[5], fhi[6], fhi[7]);
    }
}

// ---------------- 6. conv3: 32 -> 1, 3x3 SAME ----------------
__global__ void k_conv3(const float* __restrict__ w3,
                        const float* __restrict__ b3,
                        float* __restrict__ out_img) {
    __shared__ float s_w[NC * 9];
    int tid = threadIdx.x;
    for (int k = tid; k < NC * 9; k += 256) s_w[k] = w3[k];
    __syncthreads();
    int idx = blockIdx.x * 256 + tid;
    int b = idx >> 16;
    int p = idx & (SS - 1);
    int i = p >> 8, j = p & 255;
    float acc = b3[0];
    for (int ic = 0; ic < NC; ++ic) {
        const float* in = &g_h2[(b * NC + ic) << 16];
        const float* w = &s_w[ic * 9];
        #pragma unroll
        for (int ky = 0; ky < 3; ++ky) {
            int y = i + ky - 1;
            if (y < 0 || y >= SZ) continue;
            #pragma unroll
            for (int kx = 0; kx < 3; ++kx) {
                int x = j + kx - 1;
                if (x < 0 || x >= SZ) continue;
                acc += in[y * SZ + x] * w[ky * 3 + kx];
            }
        }
    }
    out_img[idx] = acc;
}

// ---------------- launch: input-order-robust dispatch ----------------
extern "C" void kernel_launch(void* const* d_in, const int* in_sizes, int n_in,
                              void* d_out, int out_size) {
    const float *x_sino = 0, *y_prev = 0, *y_cat = 0, *angles = 0, *step = 0;
    const float *w1 = 0, *b1 = 0, *w2 = 0, *b2 = 0, *w3 = 0, *b3 = 0;

    int ix = -1;
    for (int i = 0; i < n_in; ++i) if (in_sizes[i] == 51200) ix = i;
    bool dict_order = (ix == 0);

    int n262 = 0, n32 = 0, n1 = 0;
    for (int i = 0; i < n_in; ++i) {
        const float* p = (const float*)d_in[i];
        switch (in_sizes[i]) {
            case 51200: x_sino = p; break;
            case 50:    angles = p; break;
            case 576:   w1 = p; break;
            case 9216:  w2 = p; break;
            case 288:   w3 = p; break;
            case 262144:
                if (dict_order) { if (n262 == 0) y_prev = p; else y_cat = p; }
                else            { if (n262 == 0) y_cat  = p; else y_prev = p; }
                ++n262; break;
            case 32:
                if (n32 == 0) b1 = p; else b2 = p;
                ++n32; break;
            case 1:
                if (dict_order) { if (n1 == 0) step = p; else b3 = p; }
                else            { if (n1 == 0) b3   = p; else step = p; }
                ++n1; break;
            default: break;
        }
    }

    float* out_img = (float*)d_out;
    float* out_up;
    if (out_size >= 2 * BB * SS) {
        out_up = (float*)d_out + BB * SS;
    } else {
        cudaGetSymbolAddress((void**)&out_up, g_up);
    }

    k_radon<<<dim3(NA, BB, NZ), 256>>>(y_prev, angles);
    k_filter<<<dim3(NA, BB), 256>>>(x_sino);
    k_backproj<<<dim3(SZ / 2, BB), 512>>>(y_prev, angles, step, out_up);
    k_conv1<<<(BB * SS) / 256, 256>>>(out_up, y_cat, w1, b1);
    k_conv2<<<dim3(4, 32, BB), 256>>>(w2, b2);
    k_conv3<<<(BB * SS) / 256, 256>>>(w3, b3, out_img);
}

// round 8
// speedup vs baseline: 1.0261x; 1.0261x over previous
#include <cuda_runtime.h>
#include <math.h>

#define BB 4
#define NA 50
#define SZ 256
#define SS (SZ*SZ)
#define NC 32
#define PP 512
#define CEN 127.5f
#define NZ 8                       // radon band splits

typedef unsigned long long u64;

// ---- packed f32x2 helpers (sm_103a dual-rate fp32 path) ----
__device__ __forceinline__ u64 pk2(float lo, float hi) {
    u64 r; asm("mov.b64 %0, {%1, %2};" : "=l"(r) : "f"(lo), "f"(hi)); return r;
}
__device__ __forceinline__ u64 fma2(u64 a, u64 b, u64 c) {
    u64 d; asm("fma.rn.f32x2 %0, %1, %2, %3;" : "=l"(d) : "l"(a), "l"(b), "l"(c)); return d;
}
__device__ __forceinline__ void unpk2(u64 v, float& lo, float& hi) {
    asm("mov.b64 {%0, %1}, %2;" : "=f"(lo), "=f"(hi) : "l"(v));
}

// ---------------- scratch (static device allocations) ----------------
__device__ float g_part[NZ*BB*NA*SZ];    // radon partial sums per band
__device__ float g_filt[BB*NA*SZ];       // filtered sinogram (scaled)
__device__ float g_h1[BB*NC*SS];         // conv1 output
__device__ float g_h2[BB*NC*SS];         // conv2 output
__device__ float g_up[BB*SS];            // fallback y_img_update buffer

// ---------------- 1. radon forward: band-tiled, mask fused ----------------
__global__ void __launch_bounds__(256) k_radon(const float* __restrict__ yprev,
                                               const float* __restrict__ angles) {
    __shared__ float s_band[33][257];
    int a = blockIdx.x, b = blockIdx.y, z = blockIdx.z;
    int s = threadIdx.x;
    int y0 = z * 32;
    int lo = (z == 0) ? -1 : y0;
    int hi = y0 + 32;

    const float* im = &yprev[b * SS];
    float dxm = (float)s - CEN;
    #pragma unroll
    for (int i = 0; i < 33; ++i) {
        int gy = y0 + i;
        float dym = (float)gy - CEN;
        float m = (dym * dym + dxm * dxm <= 16384.0f) ? 1.0f : 0.0f;
        s_band[i][s] = (gy <= 255) ? im[gy * SZ + s] * m : 0.0f;
    }
    __syncthreads();

    float ca, sa;
    __sincosf(angles[a], &sa, &ca);
    float sf = (float)s - CEN;
    float rowA = sf * sa - CEN * ca + CEN;
    float colA = sf * ca + CEN * sa + CEN;

    float tmin, tmax;
    if (fabsf(ca) > 1e-6f) {
        float t1 = ((float)lo - 0.5f - rowA) / ca;
        float t2 = ((float)hi + 0.5f - rowA) / ca;
        tmin = fminf(t1, t2) - 1.0f;
        tmax = fmaxf(t1, t2) + 1.0f;
    } else {
        bool inb = (rowA >= (float)lo - 1.0f) && (rowA < (float)hi + 1.0f);
        tmin = inb ? 0.0f : 1.0f;
        tmax = inb ? 255.0f : 0.0f;
    }
    int ts = max(0, (int)floorf(tmin));
    int te = min(255, (int)ceilf(tmax));

    float sum = 0.0f;
    for (int t = ts; t <= te; ++t) {
        float row = rowA + (float)t * ca;
        float rf = floorf(row);
        int r0 = (int)rf;
        if (r0 < lo || r0 >= hi) continue;
        float wr = row - rf;
        float col = colA - (float)t * sa;
        float cf = floorf(col);
        int c0 = (int)cf;
        float wc = col - cf;
        int c0c = min(max(c0, 0), 255);
        int c1c = min(max(c0 + 1, 0), 255);
        float mc0 = (c0 == c0c) ? 1.0f : 0.0f;
        float mc1 = (c0 + 1 == c1c) ? 1.0f : 0.0f;
        float mr0 = (r0 >= 0) ? 1.0f : 0.0f;
        int lr = r0 - y0;
        int lrc = max(lr, 0);
        float v00 = s_band[lrc][c0c],     v01 = s_band[lrc][c1c];
        float v10 = s_band[lr + 1][c0c],  v11 = s_band[lr + 1][c1c];
        float top = mc0 * (1.0f - wc) * v00 + mc1 * wc * v01;
        float bot = mc0 * (1.0f - wc) * v10 + mc1 * wc * v11;
        sum += mr0 * (1.0f - wr) * top + wr * bot;
    }
    g_part[((z * BB + b) * NA + a) * SZ + s] = sum;
}

// ---------------- 2. ramp filter: analytic taps + fold partials ------------
__device__ __forceinline__ float hval(int m) {
    if (m == 0) return 0.5f;
    if ((m & 1) == 0) return 0.0f;
    float sv = sinf((float)M_PI * (float)m / (float)PP);
    return -2.0f / ((float)PP * (float)PP * sv * sv);
}
__global__ void k_filter(const float* __restrict__ x_sino) {
    __shared__ float sd[SZ];
    __shared__ float sh[PP];
    int a = blockIdx.x, b = blockIdx.y;
    int n = threadIdx.x;
    int base = (b * NA + a) * SZ + n;
    float d = -x_sino[base];
    #pragma unroll
    for (int z = 0; z < NZ; ++z) d += g_part[((z * BB + b) * NA + a) * SZ + n];
    sd[n] = d;
    sh[n] = hval(n);
    sh[n + 256] = hval(n + 256);
    __syncthreads();
    float acc = 0.5f * sd[n];
    int m0 = (n & 1) ^ 1;
    #pragma unroll 8
    for (int j = 0; j < 128; ++j) {
        int m = m0 + 2 * j;
        acc += sd[m] * sh[(n - m + PP) & (PP - 1)];
    }
    g_filt[base] = acc * (float)(M_PI / (2.0 * NA));
}

// ---------------- 3. backprojection + update (2 rows/block) ----------------
__global__ void __launch_bounds__(512) k_backproj(const float* __restrict__ yprev,
                                                  const float* __restrict__ angles,
                                                  const float* __restrict__ step,
                                                  float* __restrict__ out_up) {
    __shared__ float s_sino[25 * SZ];
    __shared__ float s_cos[NA], s_sin[NA];
    int b = blockIdx.y;
    int tid = threadIdx.x;
    int j = tid & 255, half = tid >> 8;
    int i = blockIdx.x * 2 + half;
    if (tid < NA) { s_cos[tid] = cosf(angles[tid]); s_sin[tid] = sinf(angles[tid]); }
    __syncthreads();
    float xx = (float)j - CEN, yy = (float)i - CEN;
    float acc = 0.0f;
    for (int ch = 0; ch < 2; ++ch) {
        for (int k = tid; k < 25 * SZ; k += 512) {
            s_sino[k] = g_filt[(b * NA + ch * 25) * SZ + k];
        }
        __syncthreads();
        #pragma unroll 5
        for (int al = 0; al < 25; ++al) {
            int a = ch * 25 + al;
            float det = xx * s_cos[a] + yy * s_sin[a] + CEN;
            float df = floorf(det);
            int i0 = (int)df;
            i0 = i0 < 0 ? 0 : (i0 > SZ - 2 ? SZ - 2 : i0);
            float w = det - (float)i0;
            float v = s_sino[al * SZ + i0] * (1.0f - w) + s_sino[al * SZ + i0 + 1] * w;
            if (det >= 0.0f && det <= (float)(SZ - 1)) acc += v;
        }
        __syncthreads();
    }
    float m = (xx*xx + yy*yy <= 16384.0f) ? 1.0f : 0.0f;
    int o = b * SS + i * SZ + j;
    out_up[o] = yprev[o] + step[0] * (acc * m);
}

// ---------------- 4. conv1: 2 -> 32, tiled, f32x2, 4px x 8oc /thread -------
#define RW 36
__global__ void __launch_bounds__(256) k_conv1(const float* __restrict__ yup,
                                               const float* __restrict__ ycat,
                                               const float* __restrict__ w1,
                                               const float* __restrict__ b1) {
    __shared__ __align__(16) float s_w2[18 * 32];      // [k][oc], k = ic*9+ky*3+kx
    __shared__ float s_b[NC];
    __shared__ __align__(16) float s_in0[10 * RW];
    __shared__ __align__(16) float s_in1[10 * RW];
    int tid = threadIdx.x;
    int b = blockIdx.z;
    int gx0 = blockIdx.x * 32 - 1;
    int gy0 = blockIdx.y * 8 - 1;
    for (int idx = tid; idx < 18 * 32; idx += 256) {
        int kk = idx >> 5, oc = idx & 31;
        s_w2[idx] = w1[oc * 18 + kk];
    }
    if (tid < NC) s_b[tid] = b1[tid];
    for (int idx = tid; idx < 10 * RW; idx += 256) {
        int rr = idx / RW, ccx = idx % RW;
        int gy = gy0 + rr, gx = gx0 + ccx;
        bool ok = (ccx < 34) && (gy >= 0) && (gy < SZ) && (gx >= 0) && (gx < SZ);
        int gi = b * SS + gy * SZ + gx;
        s_in0[idx] = ok ? yup[gi]  : 0.0f;
        s_in1[idx] = ok ? ycat[gi] : 0.0f;
    }
    __syncthreads();

    int q = tid & 7, r = (tid >> 3) & 7, og = tid >> 6;
    u64 acc2[4][4];
    #pragma unroll
    for (int op = 0; op < 4; ++op) {
        int oc0 = og * 8 + 2 * op;
        u64 bp = pk2(s_b[oc0], s_b[oc0 + 1]);
        #pragma unroll
        for (int p = 0; p < 4; ++p) acc2[op][p] = bp;
    }
    #pragma unroll
    for (int ic = 0; ic < 2; ++ic) {
        const float* inb = ic ? s_in1 : s_in0;
        const float* wb  = &s_w2[ic * 288];
        #pragma unroll
        for (int ky = 0; ky < 3; ++ky) {
            const float* rowp = inb + (r + ky) * RW + q * 4;
            float4 va = *(const float4*)rowp;
            float2 vb = *(const float2*)(rowp + 4);
            float ivf[6] = {va.x, va.y, va.z, va.w, vb.x, vb.y};
            u64 ivp[6];
            #pragma unroll
            for (int m = 0; m < 6; ++m) ivp[m] = pk2(ivf[m], ivf[m]);
            #pragma unroll
            for (int kx = 0; kx < 3; ++kx) {
                const ulonglong2 wv0 = *(const ulonglong2*)&wb[(ky*3+kx)*32 + og*8];
                const ulonglong2 wv1 = *(const ulonglong2*)&wb[(ky*3+kx)*32 + og*8 + 4];
                u64 wp[4] = {wv0.x, wv0.y, wv1.x, wv1.y};
                #pragma unroll
                for (int op = 0; op < 4; ++op)
                    #pragma unroll
                    for (int p = 0; p < 4; ++p)
                        acc2[op][p] = fma2(wp[op], ivp[kx + p], acc2[op][p]);
            }
        }
    }
    int gy = blockIdx.y * 8 + r;
    int gxb = blockIdx.x * 32 + q * 4;
    #pragma unroll
    for (int op = 0; op < 4; ++op) {
        int oc0 = og * 8 + 2 * op;
        float l0,h0,l1,h1,l2,h2,l3,h3;
        unpk2(acc2[op][0], l0, h0); unpk2(acc2[op][1], l1, h1);
        unpk2(acc2[op][2], l2, h2); unpk2(acc2[op][3], l3, h3);
        float4 vlo = make_float4(fmaxf(l0,0.f), fmaxf(l1,0.f), fmaxf(l2,0.f), fmaxf(l3,0.f));
        float4 vhi = make_float4(fmaxf(h0,0.f), fmaxf(h1,0.f), fmaxf(h2,0.f), fmaxf(h3,0.f));
        *(float4*)&g_h1[((b * NC + oc0)     << 16) + gy * SZ + gxb] = vlo;
        *(float4*)&g_h1[((b * NC + oc0 + 1) << 16) + gy * SZ + gxb] = vhi;
    }
}

// ---------------- 5. conv2: 32 -> 32 (R6 proven config: 4px/thread) --------
#define ICH 16
__global__ void __launch_bounds__(256) k_conv2(const float* __restrict__ w2,
                                               const float* __restrict__ b2) {
    __shared__ __align__(16) float s_w[ICH * 9 * 32];   // [ic][k][oc]
    __shared__ __align__(16) float s_in[ICH * 10 * RW]; // [ic][row][col]
    __shared__ float s_b[NC];
    int tid = threadIdx.x;
    int q = tid & 7, r = (tid >> 3) & 7, og = tid >> 6;
    int b = blockIdx.z;
    int gx0 = blockIdx.x * 32 - 1;
    int gy0 = blockIdx.y * 8 - 1;
    if (tid < NC) s_b[tid] = b2[tid];

    u64 acc2[4][4];
    #pragma unroll
    for (int op = 0; op < 4; ++op)
        #pragma unroll
        for (int p = 0; p < 4; ++p) acc2[op][p] = 0ULL;

    for (int cc = 0; cc < 2; ++cc) {
        int icb = cc * ICH;
        __syncthreads();
        for (int idx = tid; idx < ICH * 288; idx += 256) {
            int ic = idx / 288, rem = idx % 288;
            int k = rem >> 5, oc = rem & 31;
            s_w[idx] = w2[oc * 288 + (icb + ic) * 9 + k];
        }
        for (int idx = tid; idx < ICH * 10 * RW; idx += 256) {
            int ic = idx / (10 * RW), rem = idx % (10 * RW);
            int rr = rem / RW, ccx = rem % RW;
            int gy = gy0 + rr, gx = gx0 + ccx;
            bool ok = (ccx < 34) && (gy >= 0) && (gy < SZ) && (gx >= 0) && (gx < SZ);
            s_in[idx] = ok ? g_h1[((b * NC + icb + ic) << 16) + gy * SZ + gx] : 0.0f;
        }
        __syncthreads();

        for (int ic = 0; ic < ICH; ++ic) {
            const float* inb = &s_in[ic * 10 * RW];
            const float* wb  = &s_w[ic * 288];
            #pragma unroll
            for (int ky = 0; ky < 3; ++ky) {
                const float* rowp = inb + (r + ky) * RW + q * 4;
                float4 va = *(const float4*)rowp;
                float2 vb = *(const float2*)(rowp + 4);
                float ivf[6] = {va.x, va.y, va.z, va.w, vb.x, vb.y};
                u64 ivp[6];
                #pragma unroll
                for (int m = 0; m < 6; ++m) ivp[m] = pk2(ivf[m], ivf[m]);
                #pragma unroll
                for (int kx = 0; kx < 3; ++kx) {
                    const ulonglong2 wv0 = *(const ulonglong2*)&wb[(ky*3+kx)*32 + og*8];
                    const ulonglong2 wv1 = *(const ulonglong2*)&wb[(ky*3+kx)*32 + og*8 + 4];
                    u64 wp[4] = {wv0.x, wv0.y, wv1.x, wv1.y};
                    #pragma unroll
                    for (int op = 0; op < 4; ++op)
                        #pragma unroll
                        for (int p = 0; p < 4; ++p)
                            acc2[op][p] = fma2(wp[op], ivp[kx + p], acc2[op][p]);
                }
            }
        }
    }
    int gy = blockIdx.y * 8 + r;
    int gxb = blockIdx.x * 32 + q * 4;
    #pragma unroll
    for (int op = 0; op < 4; ++op) {
        int oc0 = og * 8 + 2 * op;
        float blo = s_b[oc0], bhi = s_b[oc0 + 1];
        float l0,h0,l1,h1,l2,h2,l3,h3;
        unpk2(acc2[op][0], l0, h0); unpk2(acc2[op][1], l1, h1);
        unpk2(acc2[op][2], l2, h2); unpk2(acc2[op][3], l3, h3);
        float4 vlo = make_float4(fmaxf(l0+blo,0.f), fmaxf(l1+blo,0.f),
                                 fmaxf(l2+blo,0.f), fmaxf(l3+blo,0.f));
        float4 vhi = make_float4(fmaxf(h0+bhi,0.f), fmaxf(h1+bhi,0.f),
                                 fmaxf(h2+bhi,0.f), fmaxf(h3+bhi,0.f));
        *(float4*)&g_h2[((b * NC + oc0)     << 16) + gy * SZ + gxb] = vlo;
        *(float4*)&g_h2[((b * NC + oc0 + 1) << 16) + gy * SZ + gxb] = vhi;
    }
}

// ---------------- 6. conv3: 32 -> 1, smem-chunked tiles --------------------
__global__ void __launch_bounds__(256) k_conv3(const float* __restrict__ w3,
                                               const float* __restrict__ b3,
                                               float* __restrict__ out_img) {
    __shared__ float s_w[NC * 9];
    __shared__ __align__(16) float s_in[8 * 10 * RW];
    int tid = threadIdx.x;
    int b = blockIdx.z;
    int gx0 = blockIdx.x * 32 - 1;
    int gy0 = blockIdx.y * 8 - 1;
    for (int k = tid; k < NC * 9; k += 256) s_w[k] = w3[k];

    int jl = tid & 31, il = tid >> 5;
    float acc = b3[0];
    for (int cc = 0; cc < 4; ++cc) {
        __syncthreads();
        for (int idx = tid; idx < 8 * 10 * RW; idx += 256) {
            int ic = idx / (10 * RW), rem = idx % (10 * RW);
            int rr = rem / RW, ccx = rem % RW;
            int gy = gy0 + rr, gx = gx0 + ccx;
            bool ok = (ccx < 34) && (gy >= 0) && (gy < SZ) && (gx >= 0) && (gx < SZ);
            s_in[idx] = ok ? g_h2[((b * NC + cc * 8 + ic) << 16) + gy * SZ + gx] : 0.0f;
        }
        __syncthreads();
        #pragma unroll
        for (int ic = 0; ic < 8; ++ic) {
            const float* inb = &s_in[ic * 10 * RW];
            const float* w = &s_w[(cc * 8 + ic) * 9];
            #pragma unroll
            for (int ky = 0; ky < 3; ++ky) {
                const float* rowp = inb + (il + ky) * RW + jl;
                acc += rowp[0] * w[ky*3] + rowp[1] * w[ky*3+1] + rowp[2] * w[ky*3+2];
            }
        }
    }
    int gy = blockIdx.y * 8 + il;
    int gx = blockIdx.x * 32 + jl;
    out_img[b * SS + gy * SZ + gx] = acc;
}

// ---------------- launch: input-order-robust dispatch ----------------
extern "C" void kernel_launch(void* const* d_in, const int* in_sizes, int n_in,
                              void* d_out, int out_size) {
    const float *x_sino = 0, *y_prev = 0, *y_cat = 0, *angles = 0, *step = 0;
    const float *w1 = 0, *b1 = 0, *w2 = 0, *b2 = 0, *w3 = 0, *b3 = 0;

    int ix = -1;
    for (int i = 0; i < n_in; ++i) if (in_sizes[i] == 51200) ix = i;
    bool dict_order = (ix == 0);

    int n262 = 0, n32 = 0, n1 = 0;
    for (int i = 0; i < n_in; ++i) {
        const float* p = (const float*)d_in[i];
        switch (in_sizes[i]) {
            case 51200: x_sino = p; break;
            case 50:    angles = p; break;
            case 576:   w1 = p; break;
            case 9216:  w2 = p; break;
            case 288:   w3 = p; break;
            case 262144:
                if (dict_order) { if (n262 == 0) y_prev = p; else y_cat = p; }
                else            { if (n262 == 0) y_cat  = p; else y_prev = p; }
                ++n262; break;
            case 32:
                if (n32 == 0) b1 = p; else b2 = p;
                ++n32; break;
            case 1:
                if (dict_order) { if (n1 == 0) step = p; else b3 = p; }
                else            { if (n1 == 0) b3   = p; else step = p; }
                ++n1; break;
            default: break;
        }
    }

    float* out_img = (float*)d_out;
    float* out_up;
    if (out_size >= 2 * BB * SS) {
        out_up = (float*)d_out + BB * SS;
    } else {
        cudaGetSymbolAddress((void**)&out_up, g_up);
    }

    k_radon<<<dim3(NA, BB, NZ), 256>>>(y_prev, angles);
    k_filter<<<dim3(NA, BB), 256>>>(x_sino);
    k_backproj<<<dim3(SZ / 2, BB), 512>>>(y_prev, angles, step, out_up);
    k_conv1<<<dim3(8, 32, BB), 256>>>(out_up, y_cat, w1, b1);
    k_conv2<<<dim3(8, 32, BB), 256>>>(w2, b2);
    k_conv3<<<dim3(8, 32, BB), 256>>>(w3, b3, out_img);
}